// round 1
// baseline (speedup 1.0000x reference)
#include <cuda_runtime.h>
#include <math.h>

#define Bv 64
#define Tv 512
#define Dv 512
#define Hv 1024
#define FH 4096            // 4*H
#define NTv (Bv*Tv)        // 32768
#define HSTR 20            // padded smem stride for h tile (bank-conflict-free staging)
#define RECBLK 128
#define RECTHR 256
#define SMEMSZ ((Hv*HSTR + 128*128) * 4)   // 81920 + 65536 = 147456 bytes

// ---------------- scratch (device globals; no dynamic allocation allowed) ----------------
__device__ float    g_xz[(size_t)NTv * FH];   // 512 MB: precomputed x-part preactivations
__device__ float    g_y0[(size_t)NTv * Hv];   // 128 MB: layer-0 output sequence
__device__ float    g_hbuf[2][Hv][Bv];        // double-buffered h state, [k][b] layout
__device__ float    g_wr[Hv][FH];             // packed recurrent weights: wr[k][4u+g]
__device__ unsigned g_arrive = 0;
__device__ unsigned g_gen    = 0;

// ---------------- grid-wide barrier (all blocks co-resident by construction) ----------------
__device__ __forceinline__ void grid_barrier(unsigned& mygen) {
    __threadfence();            // every thread publishes its global stores
    __syncthreads();
    if (threadIdx.x == 0) {
        unsigned ticket = atomicAdd(&g_arrive, 1u);
        if (ticket == gridDim.x - 1) {
            g_arrive = 0;
            __threadfence();
            atomicAdd(&g_gen, 1u);          // release
        } else {
            while (*((volatile unsigned*)&g_gen) == mygen) { __nanosleep(32); }
        }
        __threadfence();
    }
    __syncthreads();
    mygen += 1;
}

__device__ __forceinline__ float sigf(float x) { return 1.0f / (1.0f + __expf(-x)); }

// ---------------- pack recurrent weights: g_wr[k][4u+g] = W[g*H+u][coloff+k] ----------------
__global__ __launch_bounds__(256) void pack_wr(const float* __restrict__ W, int ldw, int coloff) {
    int idx = blockIdx.x * 256 + threadIdx.x;     // 4096*256 = 1M threads, one (j, k4) each
    int j   = idx >> 8;                           // 0..4095
    int k4  = (idx & 255) << 2;                   // 0..1020
    float4 v = *(const float4*)&W[(size_t)j * ldw + coloff + k4];
    int u = j & (Hv - 1), g = j >> 10;
    int c = (u << 2) | g;
    g_wr[k4 + 0][c] = v.x;
    g_wr[k4 + 1][c] = v.y;
    g_wr[k4 + 2][c] = v.z;
    g_wr[k4 + 3][c] = v.w;
}

// ---------------- x-part GEMM: g_xz[n][j] = bias[j] + sum_k A[n][k]*W[j][k] ----------------
// A: (NT,K) row-major (lda=K). W rows j with leading dim ldw (uses cols [0,K)).
// 128x128x16 tile, 256 threads, 8x8 register tile.
__global__ __launch_bounds__(256) void xz_gemm(
    const float* __restrict__ Aext, const float* __restrict__ W,
    const float* __restrict__ bias, int K, int ldw, int a_internal)
{
    const float* A = a_internal ? g_y0 : Aext;
    __shared__ float As[16][128];
    __shared__ float Bs[16][128];
    int tid = threadIdx.x;
    int m0 = blockIdx.x * 128;
    int n0 = blockIdx.y * 128;
    int tx = tid & 15, ty = tid >> 4;
    int lr = tid >> 2;            // 0..63
    int lk = (tid & 3) << 2;      // 0,4,8,12

    float acc[8][8];
#pragma unroll
    for (int i = 0; i < 8; i++)
#pragma unroll
        for (int j = 0; j < 8; j++) acc[i][j] = 0.0f;

    for (int k0 = 0; k0 < K; k0 += 16) {
#pragma unroll
        for (int hh = 0; hh < 2; hh++) {
            int r = lr + hh * 64;
            float4 va = *(const float4*)&A[(size_t)(m0 + r) * K + k0 + lk];
            As[lk + 0][r] = va.x; As[lk + 1][r] = va.y; As[lk + 2][r] = va.z; As[lk + 3][r] = va.w;
            float4 vb = *(const float4*)&W[(size_t)(n0 + r) * ldw + k0 + lk];
            Bs[lk + 0][r] = vb.x; Bs[lk + 1][r] = vb.y; Bs[lk + 2][r] = vb.z; Bs[lk + 3][r] = vb.w;
        }
        __syncthreads();
#pragma unroll
        for (int k = 0; k < 16; k++) {
            float a[8], b[8];
#pragma unroll
            for (int i = 0; i < 4; i++) { a[i] = As[k][ty * 4 + i]; a[4 + i] = As[k][64 + ty * 4 + i]; }
#pragma unroll
            for (int j = 0; j < 4; j++) { b[j] = Bs[k][tx * 4 + j]; b[4 + j] = Bs[k][64 + tx * 4 + j]; }
#pragma unroll
            for (int i = 0; i < 8; i++)
#pragma unroll
                for (int j = 0; j < 8; j++) acc[i][j] += a[i] * b[j];
        }
        __syncthreads();
    }

    float bsv[8];
#pragma unroll
    for (int j = 0; j < 4; j++) { bsv[j] = bias[n0 + tx * 4 + j]; bsv[4 + j] = bias[n0 + 64 + tx * 4 + j]; }
#pragma unroll
    for (int i = 0; i < 8; i++) {
        int m = m0 + ((i < 4) ? (ty * 4 + i) : (64 + ty * 4 + (i - 4)));
        float* crow = &g_xz[(size_t)m * FH + n0];
#pragma unroll
        for (int j = 0; j < 8; j++) {
            int c = (j < 4) ? (tx * 4 + j) : (64 + tx * 4 + (j - 4));
            crow[c] = acc[i][j] + bsv[j];
        }
    }
}

// ---------------- persistent recurrence kernel: 512 steps, 1 grid barrier / step ----------------
// Grid 128 blocks x 256 threads (1 block/SM via 144KB smem -> all co-resident).
// Block tile: 16 batches x 32 units (x4 gates). Thread: 2 batches x 1 unit x 4 gates.
// c stays in registers for the whole sequence; h double-buffered in global (L2 via ldcg/plain st).
__global__ __launch_bounds__(RECTHR) void lstm_rec(float* __restrict__ yext, int y_internal)
{
    extern __shared__ float sm[];
    float* h_s = sm;                  // [1024][HSTR=20] (16 used)
    float* w_s = sm + Hv * HSTR;      // [128][128]
    float* y = y_internal ? g_y0 : yext;

    int tid = threadIdx.x;
    int bb  = blockIdx.x & 3;         // 4 batch-blocks
    int ub  = blockIdx.x >> 2;        // 32 unit-blocks
    int b0  = bb * 16;
    int u0  = ub * 32;
    int ul  = tid & 31;               // unit within tile
    int bp  = tid >> 5;               // batch-pair 0..7
    int u   = u0 + ul;
    int b_0 = b0 + bp * 2;
    int c0col = u0 * 4;               // gate-interleaved column base in g_wr

    // zero h buffer 0 (initial state), disjoint slices per thread
    for (int i = blockIdx.x * RECTHR + tid; i < Hv * Bv; i += RECBLK * RECTHR)
        ((float*)g_hbuf)[i] = 0.0f;

    float cc0 = 0.0f, cc1 = 0.0f;
    unsigned mygen = *((volatile unsigned*)&g_gen);   // stable at launch start
    grid_barrier(mygen);

    int p = 0;
    const size_t xz_bstride = (size_t)Tv * FH;
    const float* xzr0 = g_xz + (size_t)b_0 * xz_bstride;

    for (int t = 0; t < Tv; t++) {
        // stage h_prev tile (16 batches x 1024) -> smem [k][16]; L2 reads (bypass stale L1)
        {
            int kk  = tid >> 2;             // 0..63
            int bl4 = (tid & 3) << 2;       // 0,4,8,12
#pragma unroll
            for (int pass = 0; pass < 16; pass++) {
                int k = kk + pass * 64;
                float4 v = __ldcg((const float4*)&g_hbuf[p][k][b0 + bl4]);
                *(float4*)&h_s[k * HSTR + bl4] = v;
            }
        }

        // init z with precomputed x-part (+bias already folded in)
        const float* x0 = xzr0 + (size_t)t * FH;
        const float* x1 = x0 + xz_bstride;
        float z00 = x0[u], z01 = x0[Hv + u], z02 = x0[2 * Hv + u], z03 = x0[3 * Hv + u];
        float z10 = x1[u], z11 = x1[Hv + u], z12 = x1[2 * Hv + u], z13 = x1[3 * Hv + u];

        // accumulate h @ Wh^T over K=1024 in 8 chunks of 128 (W chunk staged in smem)
#pragma unroll 1
        for (int kc = 0; kc < 8; kc++) {
            {
                int kk = tid >> 5;          // 0..7
                int c4 = (tid & 31) << 2;   // 0..124
#pragma unroll
                for (int pass = 0; pass < 16; pass++) {
                    int kr = kk + pass * 8;
                    float4 v = *(const float4*)&g_wr[kc * 128 + kr][c0col + c4];
                    *(float4*)&w_s[kr * 128 + c4] = v;
                }
            }
            __syncthreads();
            const float* hp = &h_s[(kc * 128) * HSTR + bp * 2];
            const float* wp = &w_s[ul * 4];
#pragma unroll 8
            for (int k = 0; k < 128; k++) {
                float2 hh = *(const float2*)(hp + k * HSTR);     // broadcast within warp
                float4 ww = *(const float4*)(wp + k * 128);      // conflict-free
                z00 += hh.x * ww.x; z01 += hh.x * ww.y; z02 += hh.x * ww.z; z03 += hh.x * ww.w;
                z10 += hh.y * ww.x; z11 += hh.y * ww.y; z12 += hh.y * ww.z; z13 += hh.y * ww.w;
            }
            __syncthreads();
        }

        // gates (torch order i,f,o,g), update c (registers) and h
        float iv0 = sigf(z00), fv0 = sigf(z01), ov0 = sigf(z02), gv0 = tanhf(z03);
        cc0 = fv0 * cc0 + iv0 * gv0;
        float hv0 = ov0 * tanhf(cc0);
        float iv1 = sigf(z10), fv1 = sigf(z11), ov1 = sigf(z12), gv1 = tanhf(z13);
        cc1 = fv1 * cc1 + iv1 * gv1;
        float hv1 = ov1 * tanhf(cc1);

        g_hbuf[p ^ 1][u][b_0]     = hv0;
        g_hbuf[p ^ 1][u][b_0 + 1] = hv1;
        y[(size_t)b_0 * (Tv * Hv) + (size_t)t * Hv + u]       = hv0;
        y[(size_t)(b_0 + 1) * (Tv * Hv) + (size_t)t * Hv + u] = hv1;

        p ^= 1;
        grid_barrier(mygen);
    }
}

// ---------------- entry point ----------------
extern "C" void kernel_launch(void* const* d_in, const int* in_sizes, int n_in,
                              void* d_out, int out_size) {
    (void)in_sizes; (void)n_in; (void)out_size;
    const float* x  = (const float*)d_in[0];
    const float* W0 = (const float*)d_in[1];
    const float* b0 = (const float*)d_in[2];
    const float* W1 = (const float*)d_in[3];
    const float* b1 = (const float*)d_in[4];
    float* out = (float*)d_out;

    cudaFuncSetAttribute(lstm_rec, cudaFuncAttributeMaxDynamicSharedMemorySize, SMEMSZ);

    dim3 gemm_grid(NTv / 128, FH / 128);

    // ---- layer 0 ----
    pack_wr<<<4096, 256>>>(W0, Dv + Hv, Dv);                    // recurrent cols of W0
    xz_gemm<<<gemm_grid, 256>>>(x, W0, b0, Dv, Dv + Hv, 0);     // xz = x @ W0x^T + b0
    lstm_rec<<<RECBLK, RECTHR, SMEMSZ>>>(out, 1);               // -> g_y0

    // ---- layer 1 ----
    pack_wr<<<4096, 256>>>(W1, 2 * Hv, Hv);                     // recurrent cols of W1
    xz_gemm<<<gemm_grid, 256>>>(x, W1, b1, Hv, 2 * Hv, 1);      // xz = y0 @ W1x^T + b1
    lstm_rec<<<RECBLK, RECTHR, SMEMSZ>>>(out, 0);               // -> d_out
}